// round 3
// baseline (speedup 1.0000x reference)
#include <cuda_runtime.h>
#include <cstdint>

#define N_TOK 8192
#define DIMD  1024
#define DIMH  4096
#define DIMO  1024
#define NEXP  8
#define TEMPR 2.718281828459045f

#define MAXSLOTS 17408   // 16384 assignments + 8*128 worst-case padding
#define MAXTILES 136     // MAXSLOTS / 128

#define BM 128
#define BN 128
#define BK 16

// ---------------- device scratch (static: no allocation allowed) ----------------
__device__ float g_hbuf[(size_t)MAXSLOTS * DIMH];   // relu(x@W1+b1), fp32
__device__ int   g_perm[MAXSLOTS];                  // slot -> token (-1 = padding)
__device__ float g_gate[MAXSLOTS];                  // slot -> gate weight
__device__ int   g_tope[N_TOK * 2];
__device__ float g_topw[N_TOK * 2];
__device__ int   g_cnt[NEXP];
__device__ int   g_cur[NEXP];
__device__ int   g_off[NEXP];
__device__ int   g_texp[MAXTILES];                  // row-tile -> expert (-1 = inactive)

__device__ __forceinline__ unsigned f2tf(float f) {
    unsigned u;
    asm("cvt.rna.tf32.f32 %0, %1;" : "=r"(u) : "f"(f));
    return u;
}

// ---------------- init: zero counters, poison perm/gate ----------------
__global__ void k_init() {
    int i = blockIdx.x * blockDim.x + threadIdx.x;
    if (i < MAXSLOTS) { g_perm[i] = -1; g_gate[i] = 0.f; }
    if (i < NEXP)     { g_cnt[i] = 0; g_cur[i] = 0; }
}

// ---------------- gating: scores, softmax/T, top-2, renormalize ----------------
__global__ void k_gate(const float* __restrict__ x, const float* __restrict__ Wg,
                       const float* __restrict__ bg) {
    int lane = threadIdx.x & 31;
    int tok  = blockIdx.x * 8 + (threadIdx.x >> 5);
    float acc[NEXP];
#pragma unroll
    for (int e = 0; e < NEXP; e++) acc[e] = 0.f;
    const float* xr = x + (size_t)tok * DIMD;
    for (int d = lane; d < DIMD; d += 32) {
        float xv = xr[d];
        const float4* wg = (const float4*)(Wg + d * NEXP);
        float4 w0 = wg[0], w1 = wg[1];
        acc[0] += xv * w0.x; acc[1] += xv * w0.y; acc[2] += xv * w0.z; acc[3] += xv * w0.w;
        acc[4] += xv * w1.x; acc[5] += xv * w1.y; acc[6] += xv * w1.z; acc[7] += xv * w1.w;
    }
#pragma unroll
    for (int e = 0; e < NEXP; e++) {
#pragma unroll
        for (int o = 16; o > 0; o >>= 1) acc[e] += __shfl_xor_sync(0xffffffffu, acc[e], o);
    }
    if (lane == 0) {
        float s[NEXP];
#pragma unroll
        for (int e = 0; e < NEXP; e++) s[e] = (acc[e] + bg[e]) * (1.0f / TEMPR);
        int i1 = 0;
#pragma unroll
        for (int e = 1; e < NEXP; e++) if (s[e] > s[i1]) i1 = e;
        int i2 = (i1 == 0) ? 1 : 0;
#pragma unroll
        for (int e = 0; e < NEXP; e++) if (e != i1 && s[e] > s[i2]) i2 = e;
        float m = s[i1];
        float denom = 0.f;
#pragma unroll
        for (int e = 0; e < NEXP; e++) denom += expf(s[e] - m);
        float p1 = expf(s[i1] - m) / denom;
        float p2 = expf(s[i2] - m) / denom;
        float inv = 1.f / (p1 + p2 + 1e-8f);
        g_tope[tok * 2 + 0] = i1; g_topw[tok * 2 + 0] = p1 * inv;
        g_tope[tok * 2 + 1] = i2; g_topw[tok * 2 + 1] = p2 * inv;
        atomicAdd(&g_cnt[i1], 1);
        atomicAdd(&g_cnt[i2], 1);
    }
}

// ---------------- offsets: pad each expert's count to 128-row tiles ----------------
__global__ void k_offsets() {
    int tileE[MAXTILES];
    int run = 0;
    for (int e = 0; e < NEXP; e++) {
        g_off[e] = run;
        int ntile = (g_cnt[e] + BM - 1) / BM;
        for (int t = 0; t < ntile; t++) tileE[run / BM + t] = e;
        run += ntile * BM;
    }
    int used = run / BM;
    for (int t = 0; t < MAXTILES; t++) g_texp[t] = (t < used) ? tileE[t] : -1;
}

// ---------------- scatter tokens into per-expert slot ranges ----------------
__global__ void k_scatter() {
    int i = blockIdx.x * blockDim.x + threadIdx.x;
    if (i >= N_TOK * 2) return;
    int e = g_tope[i];
    int pos = atomicAdd(&g_cur[e], 1);
    int slot = g_off[e] + pos;
    g_perm[slot] = i >> 1;
    g_gate[slot] = g_topw[i];
}

// ---------------- grouped GEMM: 128x128 tile, tf32 mma.sync, double-buffered ----------------
// FIRST:  A = gathered x rows [*,1024], B = W1[e] [1024,4096], epi: +b1, relu -> g_hbuf
// !FIRST: A = g_hbuf rows [*,4096],    B = W2[e] [4096,1024], epi: atomicAdd(out, w*(acc+b2))
template<int KDIM, int NDIM, bool FIRST>
__global__ __launch_bounds__(256) void k_gemm(
    const float* __restrict__ Ain,
    const float* __restrict__ Wall,
    const float* __restrict__ bias,
    float* __restrict__ Out)
{
    __shared__ unsigned As[2][BM * 20];    // 16 tf32 cols + pad 4 (conflict-free frag loads)
    __shared__ unsigned Bs[2][BK * 136];   // 128 tf32 cols + pad 8 (conflict-free frag loads)

    const int tileM = blockIdx.x;
    const int e = g_texp[tileM];
    if (e < 0) return;
    const int rowBase = tileM * BM;
    const int colBase = blockIdx.y * BN;

    const float* Bmat = Wall + (size_t)e * KDIM * NDIM;
    const float* A = FIRST ? Ain : (const float*)g_hbuf;
    const int lda = FIRST ? DIMD : DIMH;

    const int tid  = threadIdx.x;
    const int lane = tid & 31;
    const int warp = tid >> 5;
    const int warpM = warp & 1;   // 2 warps along M (64 rows each)
    const int warpN = warp >> 1;  // 4 warps along N (32 cols each)

    // staging maps: A tile 128x16 (each thread 2 x float4), B tile 16x128 (each thread 2 x float4)
    const int ar  = tid >> 2;          // 0..63
    const int ac  = (tid & 3) * 4;     // 0,4,8,12
    const int brr = tid >> 5;          // 0..7
    const int bcc = (tid & 31) * 4;    // 0..124

    const float* aptr[2];
#pragma unroll
    for (int p = 0; p < 2; p++) {
        int r = rowBase + ar + p * 64;
        if (FIRST) {
            int t = g_perm[r];
            if (t < 0) t = 0;          // padding: clamped load, gate=0 kills it later
            aptr[p] = A + (size_t)t * lda + ac;
        } else {
            aptr[p] = A + (size_t)r * lda + ac;
        }
    }
    const float* bptr[2];
#pragma unroll
    for (int p = 0; p < 2; p++)
        bptr[p] = Bmat + (size_t)(brr + p * 8) * NDIM + colBase + bcc;

    float acc[4][4][4];
#pragma unroll
    for (int mt = 0; mt < 4; mt++)
#pragma unroll
        for (int nt = 0; nt < 4; nt++)
#pragma unroll
            for (int i = 0; i < 4; i++) acc[mt][nt][i] = 0.f;

    float4 aR[2], bR[2];
    // prologue: stage k-block 0
#pragma unroll
    for (int p = 0; p < 2; p++) {
        aR[p] = *(const float4*)(aptr[p]);
        bR[p] = *(const float4*)(bptr[p]);
    }
#pragma unroll
    for (int p = 0; p < 2; p++) {
        uint4 va = make_uint4(f2tf(aR[p].x), f2tf(aR[p].y), f2tf(aR[p].z), f2tf(aR[p].w));
        *(uint4*)&As[0][(ar + p * 64) * 20 + ac] = va;
        uint4 vb = make_uint4(f2tf(bR[p].x), f2tf(bR[p].y), f2tf(bR[p].z), f2tf(bR[p].w));
        *(uint4*)&Bs[0][(brr + p * 8) * 136 + bcc] = vb;
    }
    __syncthreads();

    const int NKB = KDIM / BK;
    for (int kb = 0; kb < NKB; kb++) {
        const int cur = kb & 1;
        if (kb + 1 < NKB) {
            const int k0 = (kb + 1) * BK;
#pragma unroll
            for (int p = 0; p < 2; p++) {
                aR[p] = *(const float4*)(aptr[p] + k0);
                bR[p] = *(const float4*)(bptr[p] + (size_t)k0 * NDIM);
            }
        }
#pragma unroll
        for (int ks = 0; ks < 2; ks++) {
            const int kk = ks * 8;
            unsigned afr[4][4], bfr[4][2];
#pragma unroll
            for (int mt = 0; mt < 4; mt++) {
                int r0 = (warpM * 64 + mt * 16 + (lane >> 2)) * 20;
                int cA = kk + (lane & 3);
                afr[mt][0] = As[cur][r0 + cA];
                afr[mt][1] = As[cur][r0 + 160 + cA];       // +8 rows
                afr[mt][2] = As[cur][r0 + cA + 4];
                afr[mt][3] = As[cur][r0 + 160 + cA + 4];
            }
#pragma unroll
            for (int nt = 0; nt < 4; nt++) {
                int cB = warpN * 32 + nt * 8 + (lane >> 2);
                int rB = (kk + (lane & 3)) * 136;
                bfr[nt][0] = Bs[cur][rB + cB];
                bfr[nt][1] = Bs[cur][rB + 4 * 136 + cB];   // +4 k-rows
            }
#pragma unroll
            for (int mt = 0; mt < 4; mt++)
#pragma unroll
                for (int nt = 0; nt < 4; nt++)
                    asm volatile(
                        "mma.sync.aligned.m16n8k8.row.col.f32.tf32.tf32.f32 "
                        "{%0,%1,%2,%3},{%4,%5,%6,%7},{%8,%9},{%0,%1,%2,%3};"
                        : "+f"(acc[mt][nt][0]), "+f"(acc[mt][nt][1]),
                          "+f"(acc[mt][nt][2]), "+f"(acc[mt][nt][3])
                        : "r"(afr[mt][0]), "r"(afr[mt][1]), "r"(afr[mt][2]), "r"(afr[mt][3]),
                          "r"(bfr[nt][0]), "r"(bfr[nt][1]));
        }
        if (kb + 1 < NKB) {
            const int nxt = cur ^ 1;
#pragma unroll
            for (int p = 0; p < 2; p++) {
                uint4 va = make_uint4(f2tf(aR[p].x), f2tf(aR[p].y), f2tf(aR[p].z), f2tf(aR[p].w));
                *(uint4*)&As[nxt][(ar + p * 64) * 20 + ac] = va;
                uint4 vb = make_uint4(f2tf(bR[p].x), f2tf(bR[p].y), f2tf(bR[p].z), f2tf(bR[p].w));
                *(uint4*)&Bs[nxt][(brr + p * 8) * 136 + bcc] = vb;
            }
        }
        __syncthreads();
    }

    // epilogue
    if (FIRST) {
        const float* be = bias + e * NDIM;
#pragma unroll
        for (int mt = 0; mt < 4; mt++) {
#pragma unroll
            for (int half = 0; half < 2; half++) {
                int r = rowBase + warpM * 64 + mt * 16 + (lane >> 2) + half * 8;
#pragma unroll
                for (int nt = 0; nt < 4; nt++) {
                    int c = colBase + warpN * 32 + nt * 8 + (lane & 3) * 2;
                    float v0 = acc[mt][nt][half * 2 + 0] + be[c];
                    float v1 = acc[mt][nt][half * 2 + 1] + be[c + 1];
                    v0 = v0 > 0.f ? v0 : 0.f;
                    v1 = v1 > 0.f ? v1 : 0.f;
                    *(float2*)&g_hbuf[(size_t)r * DIMH + c] = make_float2(v0, v1);
                }
            }
        }
    } else {
        const float* be = bias + e * NDIM;
#pragma unroll
        for (int mt = 0; mt < 4; mt++) {
#pragma unroll
            for (int half = 0; half < 2; half++) {
                int slot = rowBase + warpM * 64 + mt * 16 + (lane >> 2) + half * 8;
                int tokn = g_perm[slot];
                if (tokn < 0) continue;
                float w = g_gate[slot];
#pragma unroll
                for (int nt = 0; nt < 4; nt++) {
                    int c = colBase + warpN * 32 + nt * 8 + (lane & 3) * 2;
                    atomicAdd(&Out[(size_t)tokn * DIMO + c],
                              w * (acc[mt][nt][half * 2 + 0] + be[c]));
                    atomicAdd(&Out[(size_t)tokn * DIMO + c + 1],
                              w * (acc[mt][nt][half * 2 + 1] + be[c + 1]));
                }
            }
        }
    }
}

// ---------------- launch ----------------
extern "C" void kernel_launch(void* const* d_in, const int* in_sizes, int n_in,
                              void* d_out, int out_size) {
    const float* x  = (const float*)d_in[0];
    const float* Wg = (const float*)d_in[1];
    const float* bg = (const float*)d_in[2];
    const float* W1 = (const float*)d_in[3];
    const float* b1 = (const float*)d_in[4];
    const float* W2 = (const float*)d_in[5];
    const float* b2 = (const float*)d_in[6];
    float* out = (float*)d_out;

    cudaMemsetAsync(d_out, 0, (size_t)N_TOK * DIMO * sizeof(float));
    k_init<<<(MAXSLOTS + 255) / 256, 256>>>();
    k_gate<<<N_TOK / 8, 256>>>(x, Wg, bg);
    k_offsets<<<1, 1>>>();
    k_scatter<<<(N_TOK * 2 + 255) / 256, 256>>>();
    k_gemm<DIMD, DIMH, true ><<<dim3(MAXTILES, DIMH / BN), 256>>>(x, W1, b1, nullptr);
    k_gemm<DIMH, DIMO, false><<<dim3(MAXTILES, DIMO / BN), 256>>>(x, W2, b2, out);
}

// round 7
// speedup vs baseline: 2.6824x; 2.6824x over previous
#include <cuda_runtime.h>
#include <cuda_fp16.h>
#include <cstdint>

#define N_TOK 8192
#define DIMD  1024
#define DIMH  4096
#define DIMO  1024
#define NEXP  8
#define TEMPR 2.718281828459045f

#define MAXSLOTS 17408
#define MAXTILES 136

#define BM 128
#define BN 128
#define BK 32          // halfs per k-block (2 x m16n8k16)

// ---------------- device scratch (static) ----------------
__device__ __half g_hbuf[(size_t)MAXSLOTS * DIMH];          // relu(x@W1+b1), fp16
__device__ __half g_xh  [(size_t)N_TOK * DIMD];             // x in fp16
__device__ __half g_w1t [(size_t)NEXP * DIMH * DIMD];       // W1^T: [E][H][D] K-major
__device__ __half g_w2t [(size_t)NEXP * DIMO * DIMH];       // W2^T: [E][O][H] K-major
__device__ int   g_perm[MAXSLOTS];
__device__ float g_gate[MAXSLOTS];
__device__ int   g_tope[N_TOK * 2];
__device__ float g_topw[N_TOK * 2];
__device__ int   g_cnt[NEXP];
__device__ int   g_cur[NEXP];
__device__ int   g_off[NEXP];
__device__ int   g_texp[MAXTILES];

// ---------------- one-time converts (run every launch; deterministic) ----------------
__global__ void k_cvt_x(const float* __restrict__ x) {
    int i = blockIdx.x * blockDim.x + threadIdx.x;          // i indexes float4
    float4 v = ((const float4*)x)[i];
    __half2* o = (__half2*)&g_xh[(size_t)i * 4];
    o[0] = __floats2half2_rn(v.x, v.y);
    o[1] = __floats2half2_rn(v.z, v.w);
}

// transpose+convert: in [E][K][N] fp32 -> out [E][N][K] half
template<int K, int N>
__global__ void k_tr(const float* __restrict__ in, __half* __restrict__ out) {
    __shared__ float tile[32][33];
    const int e  = blockIdx.z;
    const int k0 = blockIdx.x * 32;
    const int n0 = blockIdx.y * 32;
    const int tx = threadIdx.x, ty = threadIdx.y;           // 32 x 8
    const float* src = in + (size_t)e * K * N;
    __half* dst = out + (size_t)e * N * K;
#pragma unroll
    for (int i = 0; i < 4; i++)
        tile[ty + i * 8][tx] = src[(size_t)(k0 + ty + i * 8) * N + n0 + tx];
    __syncthreads();
#pragma unroll
    for (int i = 0; i < 4; i++)
        dst[(size_t)(n0 + ty + i * 8) * K + k0 + tx] = __float2half(tile[tx][ty + i * 8]);
}

// ---------------- routing (validated in R3) ----------------
__global__ void k_init() {
    int i = blockIdx.x * blockDim.x + threadIdx.x;
    if (i < MAXSLOTS) { g_perm[i] = -1; g_gate[i] = 0.f; }
    if (i < NEXP)     { g_cnt[i] = 0; g_cur[i] = 0; }
}

__global__ void k_gate(const float* __restrict__ x, const float* __restrict__ Wg,
                       const float* __restrict__ bg) {
    int lane = threadIdx.x & 31;
    int tok  = blockIdx.x * 8 + (threadIdx.x >> 5);
    float acc[NEXP];
#pragma unroll
    for (int e = 0; e < NEXP; e++) acc[e] = 0.f;
    const float* xr = x + (size_t)tok * DIMD;
    for (int d = lane; d < DIMD; d += 32) {
        float xv = xr[d];
        const float4* wg = (const float4*)(Wg + d * NEXP);
        float4 w0 = wg[0], w1 = wg[1];
        acc[0] += xv * w0.x; acc[1] += xv * w0.y; acc[2] += xv * w0.z; acc[3] += xv * w0.w;
        acc[4] += xv * w1.x; acc[5] += xv * w1.y; acc[6] += xv * w1.z; acc[7] += xv * w1.w;
    }
#pragma unroll
    for (int e = 0; e < NEXP; e++) {
#pragma unroll
        for (int o = 16; o > 0; o >>= 1) acc[e] += __shfl_xor_sync(0xffffffffu, acc[e], o);
    }
    if (lane == 0) {
        float s[NEXP];
#pragma unroll
        for (int e = 0; e < NEXP; e++) s[e] = (acc[e] + bg[e]) * (1.0f / TEMPR);
        int i1 = 0;
#pragma unroll
        for (int e = 1; e < NEXP; e++) if (s[e] > s[i1]) i1 = e;
        int i2 = (i1 == 0) ? 1 : 0;
#pragma unroll
        for (int e = 0; e < NEXP; e++) if (e != i1 && s[e] > s[i2]) i2 = e;
        float m = s[i1];
        float denom = 0.f;
#pragma unroll
        for (int e = 0; e < NEXP; e++) denom += expf(s[e] - m);
        float p1 = expf(s[i1] - m) / denom;
        float p2 = expf(s[i2] - m) / denom;
        float inv = 1.f / (p1 + p2 + 1e-8f);
        g_tope[tok * 2 + 0] = i1; g_topw[tok * 2 + 0] = p1 * inv;
        g_tope[tok * 2 + 1] = i2; g_topw[tok * 2 + 1] = p2 * inv;
        atomicAdd(&g_cnt[i1], 1);
        atomicAdd(&g_cnt[i2], 1);
    }
}

__global__ void k_offsets() {
    int tileE[MAXTILES];
    int run = 0;
    for (int e = 0; e < NEXP; e++) {
        g_off[e] = run;
        int ntile = (g_cnt[e] + BM - 1) / BM;
        for (int t = 0; t < ntile; t++) tileE[run / BM + t] = e;
        run += ntile * BM;
    }
    int used = run / BM;
    for (int t = 0; t < MAXTILES; t++) g_texp[t] = (t < used) ? tileE[t] : -1;
}

__global__ void k_scatter() {
    int i = blockIdx.x * blockDim.x + threadIdx.x;
    if (i >= N_TOK * 2) return;
    int e = g_tope[i];
    int pos = atomicAdd(&g_cur[e], 1);
    int slot = g_off[e] + pos;
    g_perm[slot] = i >> 1;
    g_gate[slot] = g_topw[i];
}

// smem word index with XOR swizzle: 16-word (32-half) rows, chunk j ^= (r>>1)&3
__device__ __forceinline__ int swz(int r, int w) {
    return (r << 4) + ((((w >> 2) ^ ((r >> 1) & 3)) << 2)) + (w & 3);
}

// ---------------- fp16 grouped GEMM, mma.sync m16n8k16 ----------------
// FIRST:  A = gathered g_xh rows [*,1024], B = g_w1t[e], epi: relu(acc+b1) -> g_hbuf (half)
// !FIRST: A = g_hbuf rows [*,4096],        B = g_w2t[e], epi: atomicAdd(out, w*(acc+b2))
template<int KDIM, int NDIM, bool FIRST>
__global__ __launch_bounds__(256, 2) void k_gemm(
    const __half* __restrict__ Bt,
    const float* __restrict__ bias,
    float* __restrict__ Out)
{
    __shared__ unsigned As[2][BM * 16];     // 128 rows x 16 words (32 halfs), swizzled
    __shared__ unsigned Bs[2][BN * 16];

    const int tileM = blockIdx.x;
    const int e = g_texp[tileM];
    if (e < 0) return;
    const int rowBase = tileM * BM;
    const int colBase = blockIdx.y * BN;

    const int tid  = threadIdx.x;
    const int lane = tid & 31;
    const int warp = tid >> 5;
    const int warpM = warp & 1;
    const int warpN = warp >> 1;

    // staging: thread t -> rows (t>>2) and (t>>2)+64, chunk j = t&3 (16B = 8 halfs)
    const int sr = tid >> 2;
    const int sj = tid & 3;
    const __half* A = FIRST ? g_xh : g_hbuf;
    const __half* aPtr[2];
#pragma unroll
    for (int i = 0; i < 2; i++) {
        int slot = rowBase + sr + i * 64;
        int src;
        if (FIRST) { int t = g_perm[slot]; src = (t < 0) ? 0 : t; }
        else       { src = slot; }
        aPtr[i] = A + (size_t)src * KDIM + sj * 8;
    }
    const __half* Bmat = Bt + (size_t)e * NDIM * KDIM;
    const __half* bPtr[2];
#pragma unroll
    for (int i = 0; i < 2; i++)
        bPtr[i] = Bmat + (size_t)(colBase + sr + i * 64) * KDIM + sj * 8;

    // swizzled store word-offsets (16B aligned)
    int aw[2], bw[2];
#pragma unroll
    for (int i = 0; i < 2; i++) {
        aw[i] = swz(sr + i * 64, sj * 4);
        bw[i] = aw[i];
    }

    float acc[4][4][4];
#pragma unroll
    for (int mt = 0; mt < 4; mt++)
#pragma unroll
        for (int nt = 0; nt < 4; nt++)
#pragma unroll
            for (int i = 0; i < 4; i++) acc[mt][nt][i] = 0.f;

    uint4 av[2], bv[2];
    // prologue: stage k-block 0
#pragma unroll
    for (int i = 0; i < 2; i++) {
        av[i] = *(const uint4*)(aPtr[i]);
        bv[i] = *(const uint4*)(bPtr[i]);
        *(uint4*)&As[0][aw[i]] = av[i];
        *(uint4*)&Bs[0][bw[i]] = bv[i];
    }
    __syncthreads();

    const int NKB = KDIM / BK;
    for (int kb = 0; kb < NKB; kb++) {
        const int cur = kb & 1;
        if (kb + 1 < NKB) {
            const int k0 = (kb + 1) * BK;
#pragma unroll
            for (int i = 0; i < 2; i++) {
                av[i] = *(const uint4*)(aPtr[i] + k0);
                bv[i] = *(const uint4*)(bPtr[i] + k0);
            }
        }
        const unsigned* Ab = As[cur];
        const unsigned* Bb = Bs[cur];
#pragma unroll
        for (int ks = 0; ks < 2; ks++) {
            unsigned afr[4][4], bfr[4][2];
#pragma unroll
            for (int mt = 0; mt < 4; mt++) {
                int r0 = warpM * 64 + mt * 16 + (lane >> 2);
                int w0 = ks * 8 + (lane & 3);
                afr[mt][0] = Ab[swz(r0,     w0)];
                afr[mt][1] = Ab[swz(r0 + 8, w0)];
                afr[mt][2] = Ab[swz(r0,     w0 + 4)];
                afr[mt][3] = Ab[swz(r0 + 8, w0 + 4)];
            }
#pragma unroll
            for (int nt = 0; nt < 4; nt++) {
                int n0 = warpN * 32 + nt * 8 + (lane >> 2);
                int w0 = ks * 8 + (lane & 3);
                bfr[nt][0] = Bb[swz(n0, w0)];
                bfr[nt][1] = Bb[swz(n0, w0 + 4)];
            }
#pragma unroll
            for (int mt = 0; mt < 4; mt++)
#pragma unroll
                for (int nt = 0; nt < 4; nt++)
                    asm volatile(
                        "mma.sync.aligned.m16n8k16.row.col.f32.f16.f16.f32 "
                        "{%0,%1,%2,%3},{%4,%5,%6,%7},{%8,%9},{%0,%1,%2,%3};"
                        : "+f"(acc[mt][nt][0]), "+f"(acc[mt][nt][1]),
                          "+f"(acc[mt][nt][2]), "+f"(acc[mt][nt][3])
                        : "r"(afr[mt][0]), "r"(afr[mt][1]), "r"(afr[mt][2]), "r"(afr[mt][3]),
                          "r"(bfr[nt][0]), "r"(bfr[nt][1]));
        }
        if (kb + 1 < NKB) {
            const int nxt = cur ^ 1;
#pragma unroll
            for (int i = 0; i < 2; i++) {
                *(uint4*)&As[nxt][aw[i]] = av[i];
                *(uint4*)&Bs[nxt][bw[i]] = bv[i];
            }
        }
        __syncthreads();
    }

    // ---------------- epilogue ----------------
    const float* be = bias + (size_t)e * NDIM;
    if (FIRST) {
#pragma unroll
        for (int mt = 0; mt < 4; mt++) {
#pragma unroll
            for (int half = 0; half < 2; half++) {
                int r = rowBase + warpM * 64 + mt * 16 + (lane >> 2) + half * 8;
#pragma unroll
                for (int nt = 0; nt < 4; nt++) {
                    int c = colBase + warpN * 32 + nt * 8 + (lane & 3) * 2;
                    float v0 = acc[mt][nt][half * 2 + 0] + be[c];
                    float v1 = acc[mt][nt][half * 2 + 1] + be[c + 1];
                    v0 = v0 > 0.f ? v0 : 0.f;
                    v1 = v1 > 0.f ? v1 : 0.f;
                    *(__half2*)&g_hbuf[(size_t)r * DIMH + c] = __floats2half2_rn(v0, v1);
                }
            }
        }
    } else {
#pragma unroll
        for (int mt = 0; mt < 4; mt++) {
#pragma unroll
            for (int half = 0; half < 2; half++) {
                int slot = rowBase + warpM * 64 + mt * 16 + (lane >> 2) + half * 8;
                int tokn = g_perm[slot];
                if (tokn < 0) continue;
                float w = g_gate[slot];
#pragma unroll
                for (int nt = 0; nt < 4; nt++) {
                    int c = colBase + warpN * 32 + nt * 8 + (lane & 3) * 2;
                    atomicAdd(&Out[(size_t)tokn * DIMO + c],
                              w * (acc[mt][nt][half * 2 + 0] + be[c]));
                    atomicAdd(&Out[(size_t)tokn * DIMO + c + 1],
                              w * (acc[mt][nt][half * 2 + 1] + be[c + 1]));
                }
            }
        }
    }
}

// ---------------- launch ----------------
extern "C" void kernel_launch(void* const* d_in, const int* in_sizes, int n_in,
                              void* d_out, int out_size) {
    const float* x  = (const float*)d_in[0];
    const float* Wg = (const float*)d_in[1];
    const float* bg = (const float*)d_in[2];
    const float* W1 = (const float*)d_in[3];
    const float* b1 = (const float*)d_in[4];
    const float* W2 = (const float*)d_in[5];
    const float* b2 = (const float*)d_in[6];
    float* out = (float*)d_out;

    __half *xh, *w1t, *w2t;
    cudaGetSymbolAddress((void**)&xh,  g_xh);
    cudaGetSymbolAddress((void**)&w1t, g_w1t);
    cudaGetSymbolAddress((void**)&w2t, g_w2t);

    cudaMemsetAsync(d_out, 0, (size_t)N_TOK * DIMO * sizeof(float));
    k_init<<<(MAXSLOTS + 255) / 256, 256>>>();
    k_cvt_x<<<(N_TOK * DIMD / 4 + 255) / 256, 256>>>(x);
    k_tr<DIMD, DIMH><<<dim3(DIMD / 32, DIMH / 32, NEXP), dim3(32, 8)>>>(W1, w1t);
    k_tr<DIMH, DIMO><<<dim3(DIMH / 32, DIMO / 32, NEXP), dim3(32, 8)>>>(W2, w2t);
    k_gate<<<N_TOK / 8, 256>>>(x, Wg, bg);
    k_offsets<<<1, 1>>>();
    k_scatter<<<(N_TOK * 2 + 255) / 256, 256>>>();
    k_gemm<DIMD, DIMH, true ><<<dim3(MAXTILES, DIMH / BN), 256>>>(w1t, b1, nullptr);
    k_gemm<DIMH, DIMO, false><<<dim3(MAXTILES, DIMO / BN), 256>>>(w2t, b2, out);
}

// round 9
// speedup vs baseline: 3.4973x; 1.3038x over previous
#include <cuda_runtime.h>
#include <cuda_fp16.h>
#include <cstdint>

#define N_TOK 8192
#define DIMD  1024
#define DIMH  4096
#define DIMO  1024
#define NEXP  8
#define TEMPR 2.718281828459045f

#define MAXSLOTS 17408
#define MAXTILES 136

#define BM 128
#define BN 128
#define BK 64                   // halfs per k-block (4 x m16n8k16)
#define NSTAGE 3
#define STG_A_BYTES (BM * BK * 2)          // 16384
#define STG_BYTES   (2 * STG_A_BYTES)      // A + B = 32768
#define SMEM_TOT    (NSTAGE * STG_BYTES)   // 98304

// ---------------- device scratch (static) ----------------
__device__ __half g_hbuf[(size_t)MAXSLOTS * DIMH];
__device__ __half g_xh  [(size_t)N_TOK * DIMD];
__device__ __half g_w1t [(size_t)NEXP * DIMH * DIMD];       // W1^T: [E][H][D] K-major
__device__ __half g_w2t [(size_t)NEXP * DIMO * DIMH];       // W2^T: [E][O][H] K-major
__device__ int   g_perm[MAXSLOTS];
__device__ float g_gate[MAXSLOTS];
__device__ int   g_tope[N_TOK * 2];
__device__ float g_topw[N_TOK * 2];
__device__ int   g_cnt[NEXP];
__device__ int   g_cur[NEXP];
__device__ int   g_off[NEXP];
__device__ int   g_texp[MAXTILES];

__device__ __forceinline__ uint32_t smem_u32(const void* p) {
    uint32_t a;
    asm("{ .reg .u64 t; cvta.to.shared.u64 t, %1; cvt.u32.u64 %0, t; }" : "=r"(a) : "l"(p));
    return a;
}
#define CPA16(dst, src) \
    asm volatile("cp.async.cg.shared.global [%0], [%1], 16;" :: "r"(dst), "l"(src))
#define CPA_COMMIT() asm volatile("cp.async.commit_group;" ::: "memory")
#define CPA_WAIT1()  asm volatile("cp.async.wait_group 1;" ::: "memory")
#define CPA_WAIT0()  asm volatile("cp.async.wait_group 0;" ::: "memory")
#define LDSM4(r, a) \
    asm volatile("ldmatrix.sync.aligned.m8n8.x4.shared.b16 {%0,%1,%2,%3}, [%4];" \
        : "=r"((r)[0]), "=r"((r)[1]), "=r"((r)[2]), "=r"((r)[3]) : "r"(a))

// ---------------- one-time converts ----------------
__global__ void k_cvt_x(const float* __restrict__ x) {
    int i = blockIdx.x * blockDim.x + threadIdx.x;
    float4 v = ((const float4*)x)[i];
    __half2* o = (__half2*)&g_xh[(size_t)i * 4];
    o[0] = __floats2half2_rn(v.x, v.y);
    o[1] = __floats2half2_rn(v.z, v.w);
}

template<int K, int N>
__global__ void k_tr(const float* __restrict__ in, __half* __restrict__ out) {
    __shared__ float tile[32][33];
    const int e  = blockIdx.z;
    const int k0 = blockIdx.x * 32;
    const int n0 = blockIdx.y * 32;
    const int tx = threadIdx.x, ty = threadIdx.y;
    const float* src = in + (size_t)e * K * N;
    __half* dst = out + (size_t)e * N * K;
#pragma unroll
    for (int i = 0; i < 4; i++)
        tile[ty + i * 8][tx] = src[(size_t)(k0 + ty + i * 8) * N + n0 + tx];
    __syncthreads();
#pragma unroll
    for (int i = 0; i < 4; i++)
        dst[(size_t)(n0 + ty + i * 8) * K + k0 + tx] = __float2half(tile[tx][ty + i * 8]);
}

// ---------------- routing ----------------
__global__ void k_init() {
    int i = blockIdx.x * blockDim.x + threadIdx.x;
    if (i < MAXSLOTS) { g_perm[i] = -1; g_gate[i] = 0.f; }
    if (i < NEXP)     { g_cnt[i] = 0; g_cur[i] = 0; }
}

__global__ void k_gate(const float* __restrict__ x, const float* __restrict__ Wg,
                       const float* __restrict__ bg) {
    int lane = threadIdx.x & 31;
    int tok  = blockIdx.x * 8 + (threadIdx.x >> 5);
    float acc[NEXP];
#pragma unroll
    for (int e = 0; e < NEXP; e++) acc[e] = 0.f;
    const float* xr = x + (size_t)tok * DIMD;
    for (int d = lane; d < DIMD; d += 32) {
        float xv = xr[d];
        const float4* wg = (const float4*)(Wg + d * NEXP);
        float4 w0 = wg[0], w1 = wg[1];
        acc[0] += xv * w0.x; acc[1] += xv * w0.y; acc[2] += xv * w0.z; acc[3] += xv * w0.w;
        acc[4] += xv * w1.x; acc[5] += xv * w1.y; acc[6] += xv * w1.z; acc[7] += xv * w1.w;
    }
#pragma unroll
    for (int e = 0; e < NEXP; e++) {
#pragma unroll
        for (int o = 16; o > 0; o >>= 1) acc[e] += __shfl_xor_sync(0xffffffffu, acc[e], o);
    }
    if (lane == 0) {
        float s[NEXP];
#pragma unroll
        for (int e = 0; e < NEXP; e++) s[e] = (acc[e] + bg[e]) * (1.0f / TEMPR);
        int i1 = 0;
#pragma unroll
        for (int e = 1; e < NEXP; e++) if (s[e] > s[i1]) i1 = e;
        int i2 = (i1 == 0) ? 1 : 0;
#pragma unroll
        for (int e = 0; e < NEXP; e++) if (e != i1 && s[e] > s[i2]) i2 = e;
        float m = s[i1];
        float denom = 0.f;
#pragma unroll
        for (int e = 0; e < NEXP; e++) denom += expf(s[e] - m);
        float p1 = expf(s[i1] - m) / denom;
        float p2 = expf(s[i2] - m) / denom;
        float inv = 1.f / (p1 + p2 + 1e-8f);
        g_tope[tok * 2 + 0] = i1; g_topw[tok * 2 + 0] = p1 * inv;
        g_tope[tok * 2 + 1] = i2; g_topw[tok * 2 + 1] = p2 * inv;
        atomicAdd(&g_cnt[i1], 1);
        atomicAdd(&g_cnt[i2], 1);
    }
}

__global__ void k_offsets() {
    int tileE[MAXTILES];
    int run = 0;
    for (int e = 0; e < NEXP; e++) {
        g_off[e] = run;
        int ntile = (g_cnt[e] + BM - 1) / BM;
        for (int t = 0; t < ntile; t++) tileE[run / BM + t] = e;
        run += ntile * BM;
    }
    int used = run / BM;
    for (int t = 0; t < MAXTILES; t++) g_texp[t] = (t < used) ? tileE[t] : -1;
}

__global__ void k_scatter() {
    int i = blockIdx.x * blockDim.x + threadIdx.x;
    if (i >= N_TOK * 2) return;
    int e = g_tope[i];
    int pos = atomicAdd(&g_cur[e], 1);
    int slot = g_off[e] + pos;
    g_perm[slot] = i >> 1;
    g_gate[slot] = g_topw[i];
}

// ---------------- fp16 grouped GEMM: cp.async 3-stage + ldmatrix + m16n8k16 ----------------
// smem tile layout (A and B identical): 128 rows x 64 halfs; 128B rows, 16B chunk
// swizzle: chunk' = chunk ^ (row & 7). Conflict-free for cp.async stores and LDSM.
template<int KDIM, int NDIM, bool FIRST>
__global__ __launch_bounds__(256, 2) void k_gemm(
    const __half* __restrict__ Bt,
    const float* __restrict__ bias,
    float* __restrict__ Out)
{
    extern __shared__ char smem[];
    const int tileM = blockIdx.y;
    const int e = g_texp[tileM];
    if (e < 0) return;
    const int rowBase = tileM * BM;
    const int colBase = blockIdx.x * BN;

    const uint32_t sb = smem_u32(smem);
    const int tid  = threadIdx.x;
    const int lane = tid & 31;
    const int warp = tid >> 5;
    const int warpM = warp & 1;
    const int warpN = warp >> 1;

    // ---- staging maps: thread t -> rows (t>>3)+32i (i=0..3), chunk t&7 ----
    const int trow = tid >> 3;          // 0..31
    const int tch  = tid & 7;           // 16B chunk in row
    const __half* A = FIRST ? g_xh : g_hbuf;
    const __half* Bmat = Bt + (size_t)e * NDIM * KDIM;

    const __half* aSrc[4];
#pragma unroll
    for (int i = 0; i < 4; i++) {
        int slot = rowBase + trow + 32 * i;
        int src;
        if (FIRST) { int t = g_perm[slot]; src = (t < 0) ? 0 : t; }
        else       { src = slot; }
        aSrc[i] = A + (size_t)src * KDIM + tch * 8;
    }
    const __half* bSrc0 = Bmat + (size_t)(colBase + trow) * KDIM + tch * 8;

    uint32_t dOff[4];                   // byte offset within a stage's A (or B) tile
#pragma unroll
    for (int i = 0; i < 4; i++) {
        int row = trow + 32 * i;
        dOff[i] = row * 128 + ((tch ^ (row & 7)) << 4);
    }

    // ---- fragment address precompute (per lane) ----
    const int laneRowOff = (lane & 7) + ((lane >> 3) & 1) * 8;  // row within 16-row tile pair
    const int csel = lane >> 4;                                  // 0..1 chunk select
    const int xr   = lane & 7;                                   // row&7 for swizzle
    uint32_t aRB[4], bRB[2];
#pragma unroll
    for (int mt = 0; mt < 4; mt++) aRB[mt] = (warpM * 64 + mt * 16 + laneRowOff) * 128;
#pragma unroll
    for (int np = 0; np < 2; np++) bRB[np] = (warpN * 32 + np * 16 + laneRowOff) * 128;

    float acc[4][4][4];
#pragma unroll
    for (int mt = 0; mt < 4; mt++)
#pragma unroll
        for (int nt = 0; nt < 4; nt++)
#pragma unroll
            for (int i = 0; i < 4; i++) acc[mt][nt][i] = 0.f;

    const int NKB = KDIM / BK;

    // ---- prologue: issue stages 0, 1 ----
#pragma unroll
    for (int s = 0; s < NSTAGE - 1; s++) {
        uint32_t stA = sb + s * STG_BYTES;
        uint32_t stB = stA + STG_A_BYTES;
#pragma unroll
        for (int i = 0; i < 4; i++) CPA16(stA + dOff[i], aSrc[i] + s * BK);
#pragma unroll
        for (int i = 0; i < 4; i++) CPA16(stB + dOff[i], bSrc0 + (size_t)(32 * i) * KDIM + s * BK);
        CPA_COMMIT();
    }

    int buf = 0;
    for (int kb = 0; kb < NKB; kb++) {
        CPA_WAIT1();
        __syncthreads();
        // issue stage kb+2 into the buffer consumed at kb-1
        if (kb + 2 < NKB) {
            int nb = buf + 2; if (nb >= NSTAGE) nb -= NSTAGE;
            uint32_t stA = sb + nb * STG_BYTES;
            uint32_t stB = stA + STG_A_BYTES;
            const int k0 = (kb + 2) * BK;
#pragma unroll
            for (int i = 0; i < 4; i++) CPA16(stA + dOff[i], aSrc[i] + k0);
#pragma unroll
            for (int i = 0; i < 4; i++) CPA16(stB + dOff[i], bSrc0 + (size_t)(32 * i) * KDIM + k0);
        }
        CPA_COMMIT();

        const uint32_t stA = sb + buf * STG_BYTES;
        const uint32_t stB = stA + STG_A_BYTES;
#pragma unroll
        for (int ks = 0; ks < 4; ks++) {
            const uint32_t sw = (uint32_t)(((2 * ks + csel) ^ xr) << 4);
            unsigned af[4][4], bf[2][4];
#pragma unroll
            for (int mt = 0; mt < 4; mt++) LDSM4(af[mt], stA + aRB[mt] + sw);
#pragma unroll
            for (int np = 0; np < 2; np++) LDSM4(bf[np], stB + bRB[np] + sw);
#pragma unroll
            for (int mt = 0; mt < 4; mt++)
#pragma unroll
                for (int nt = 0; nt < 4; nt++) {
                    const unsigned b0 = bf[nt >> 1][nt & 1];
                    const unsigned b1 = bf[nt >> 1][2 + (nt & 1)];
                    asm volatile(
                        "mma.sync.aligned.m16n8k16.row.col.f32.f16.f16.f32 "
                        "{%0,%1,%2,%3},{%4,%5,%6,%7},{%8,%9},{%0,%1,%2,%3};"
                        : "+f"(acc[mt][nt][0]), "+f"(acc[mt][nt][1]),
                          "+f"(acc[mt][nt][2]), "+f"(acc[mt][nt][3])
                        : "r"(af[mt][0]), "r"(af[mt][1]), "r"(af[mt][2]), "r"(af[mt][3]),
                          "r"(b0), "r"(b1));
                }
        }
        buf++; if (buf == NSTAGE) buf = 0;
    }
    CPA_WAIT0();

    // ---------------- epilogue ----------------
    const float* be = bias + (size_t)e * NDIM;
    if (FIRST) {
#pragma unroll
        for (int mt = 0; mt < 4; mt++) {
#pragma unroll
            for (int hh = 0; hh < 2; hh++) {
                int r = rowBase + warpM * 64 + mt * 16 + (lane >> 2) + hh * 8;
#pragma unroll
                for (int nt = 0; nt < 4; nt++) {
                    int c = colBase + warpN * 32 + nt * 8 + (lane & 3) * 2;
                    float v0 = acc[mt][nt][hh * 2 + 0] + be[c];
                    float v1 = acc[mt][nt][hh * 2 + 1] + be[c + 1];
                    v0 = v0 > 0.f ? v0 : 0.f;
                    v1 = v1 > 0.f ? v1 : 0.f;
                    *(__half2*)&g_hbuf[(size_t)r * DIMH + c] = __floats2half2_rn(v0, v1);
                }
            }
        }
    } else {
#pragma unroll
        for (int mt = 0; mt < 4; mt++) {
#pragma unroll
            for (int hh = 0; hh < 2; hh++) {
                int slot = rowBase + warpM * 64 + mt * 16 + (lane >> 2) + hh * 8;
                int tokn = g_perm[slot];
                if (tokn < 0) continue;
                float w = g_gate[slot];
#pragma unroll
                for (int nt = 0; nt < 4; nt++) {
                    int c = colBase + warpN * 32 + nt * 8 + (lane & 3) * 2;
                    atomicAdd(&Out[(size_t)tokn * DIMO + c],
                              w * (acc[mt][nt][hh * 2 + 0] + be[c]));
                    atomicAdd(&Out[(size_t)tokn * DIMO + c + 1],
                              w * (acc[mt][nt][hh * 2 + 1] + be[c + 1]));
                }
            }
        }
    }
}

// ---------------- launch ----------------
extern "C" void kernel_launch(void* const* d_in, const int* in_sizes, int n_in,
                              void* d_out, int out_size) {
    const float* x  = (const float*)d_in[0];
    const float* Wg = (const float*)d_in[1];
    const float* bg = (const float*)d_in[2];
    const float* W1 = (const float*)d_in[3];
    const float* b1 = (const float*)d_in[4];
    const float* W2 = (const float*)d_in[5];
    const float* b2 = (const float*)d_in[6];
    float* out = (float*)d_out;

    __half *w1t, *w2t;
    cudaGetSymbolAddress((void**)&w1t, g_w1t);
    cudaGetSymbolAddress((void**)&w2t, g_w2t);

    cudaFuncSetAttribute(k_gemm<DIMD, DIMH, true>,
                         cudaFuncAttributeMaxDynamicSharedMemorySize, SMEM_TOT);
    cudaFuncSetAttribute(k_gemm<DIMH, DIMO, false>,
                         cudaFuncAttributeMaxDynamicSharedMemorySize, SMEM_TOT);

    cudaMemsetAsync(d_out, 0, (size_t)N_TOK * DIMO * sizeof(float));
    k_init<<<(MAXSLOTS + 255) / 256, 256>>>();
    k_cvt_x<<<(N_TOK * DIMD / 4 + 255) / 256, 256>>>(x);
    k_tr<DIMD, DIMH><<<dim3(DIMD / 32, DIMH / 32, NEXP), dim3(32, 8)>>>(W1, w1t);
    k_tr<DIMH, DIMO><<<dim3(DIMH / 32, DIMO / 32, NEXP), dim3(32, 8)>>>(W2, w2t);
    k_gate<<<N_TOK / 8, 256>>>(x, Wg, bg);
    k_offsets<<<1, 1>>>();
    k_scatter<<<(N_TOK * 2 + 255) / 256, 256>>>();
    k_gemm<DIMD, DIMH, true ><<<dim3(DIMH / BN, MAXTILES), 256, SMEM_TOT>>>(w1t, b1, nullptr);
    k_gemm<DIMH, DIMO, false><<<dim3(DIMO / BN, MAXTILES), 256, SMEM_TOT>>>(w2t, b2, out);
}

// round 12
// speedup vs baseline: 3.5705x; 1.0209x over previous
#include <cuda_runtime.h>
#include <cuda_fp16.h>
#include <cstdint>

#define N_TOK 8192
#define DIMD  1024
#define DIMH  4096
#define DIMO  1024
#define NEXP  8
#define TEMPR 2.718281828459045f

#define MAXSLOTS 17408
#define MAXTILES 136

#define BM 128
#define BN 128
#define BK 64                   // halfs per k-block (4 x m16n8k16)
#define NSTAGE 3
#define STG_A_BYTES (BM * BK * 2)          // 16384
#define STG_BYTES   (2 * STG_A_BYTES)      // 32768
#define SMEM_TOT    (NSTAGE * STG_BYTES)   // 98304

// ---------------- device scratch (static) ----------------
__device__ __half g_hbuf[(size_t)MAXSLOTS * DIMH];
__device__ __half g_xh  [(size_t)N_TOK * DIMD];
__device__ __half g_w1t [(size_t)NEXP * DIMH * DIMD];
__device__ __half g_w2t [(size_t)NEXP * DIMO * DIMH];
__device__ int   g_perm[MAXSLOTS];
__device__ float g_gate[MAXSLOTS];
__device__ int   g_tope[N_TOK * 2];
__device__ float g_topw[N_TOK * 2];
__device__ int   g_cnt[NEXP];
__device__ int   g_cur[NEXP];
__device__ int   g_off[NEXP];
__device__ int   g_texp[MAXTILES];

__device__ __forceinline__ uint32_t smem_u32(const void* p) {
    uint32_t a;
    asm("{ .reg .u64 t; cvta.to.shared.u64 t, %1; cvt.u32.u64 %0, t; }" : "=r"(a) : "l"(p));
    return a;
}
#define CPA16(dst, src) \
    asm volatile("cp.async.cg.shared.global [%0], [%1], 16;" :: "r"(dst), "l"(src))
#define CPA_COMMIT() asm volatile("cp.async.commit_group;" ::: "memory")
#define CPA_WAIT1()  asm volatile("cp.async.wait_group 1;" ::: "memory")
#define CPA_WAIT0()  asm volatile("cp.async.wait_group 0;" ::: "memory")
#define LDSM4(r, a) \
    asm volatile("ldmatrix.sync.aligned.m8n8.x4.shared.b16 {%0,%1,%2,%3}, [%4];" \
        : "=r"((r)[0]), "=r"((r)[1]), "=r"((r)[2]), "=r"((r)[3]) : "r"(a))

// ---------------- one-time converts ----------------
__global__ void k_cvt_x(const float* __restrict__ x) {
    int i = blockIdx.x * blockDim.x + threadIdx.x;
    float4 v = ((const float4*)x)[i];
    __half2* o = (__half2*)&g_xh[(size_t)i * 4];
    o[0] = __floats2half2_rn(v.x, v.y);
    o[1] = __floats2half2_rn(v.z, v.w);
}

template<int K, int N>
__global__ void k_tr(const float* __restrict__ in, __half* __restrict__ out) {
    __shared__ float tile[32][33];
    const int e  = blockIdx.z;
    const int k0 = blockIdx.x * 32;
    const int n0 = blockIdx.y * 32;
    const int tx = threadIdx.x, ty = threadIdx.y;
    const float* src = in + (size_t)e * K * N;
    __half* dst = out + (size_t)e * N * K;
#pragma unroll
    for (int i = 0; i < 4; i++)
        tile[ty + i * 8][tx] = src[(size_t)(k0 + ty + i * 8) * N + n0 + tx];
    __syncthreads();
#pragma unroll
    for (int i = 0; i < 4; i++)
        dst[(size_t)(n0 + ty + i * 8) * K + k0 + tx] = __float2half(tile[tx][ty + i * 8]);
}

// ---------------- routing ----------------
__global__ void k_init() {
    int i = blockIdx.x * blockDim.x + threadIdx.x;
    if (i < MAXSLOTS) { g_perm[i] = -1; g_gate[i] = 0.f; }
    if (i < NEXP)     { g_cnt[i] = 0; g_cur[i] = 0; }
}

__global__ void k_gate(const float* __restrict__ x, const float* __restrict__ Wg,
                       const float* __restrict__ bg) {
    int lane = threadIdx.x & 31;
    int tok  = blockIdx.x * 8 + (threadIdx.x >> 5);
    float acc[NEXP];
#pragma unroll
    for (int e = 0; e < NEXP; e++) acc[e] = 0.f;
    const float* xr = x + (size_t)tok * DIMD;
    for (int d = lane; d < DIMD; d += 32) {
        float xv = xr[d];
        const float4* wg = (const float4*)(Wg + d * NEXP);
        float4 w0 = wg[0], w1 = wg[1];
        acc[0] += xv * w0.x; acc[1] += xv * w0.y; acc[2] += xv * w0.z; acc[3] += xv * w0.w;
        acc[4] += xv * w1.x; acc[5] += xv * w1.y; acc[6] += xv * w1.z; acc[7] += xv * w1.w;
    }
#pragma unroll
    for (int e = 0; e < NEXP; e++) {
#pragma unroll
        for (int o = 16; o > 0; o >>= 1) acc[e] += __shfl_xor_sync(0xffffffffu, acc[e], o);
    }
    if (lane == 0) {
        float s[NEXP];
#pragma unroll
        for (int e = 0; e < NEXP; e++) s[e] = (acc[e] + bg[e]) * (1.0f / TEMPR);
        int i1 = 0;
#pragma unroll
        for (int e = 1; e < NEXP; e++) if (s[e] > s[i1]) i1 = e;
        int i2 = (i1 == 0) ? 1 : 0;
#pragma unroll
        for (int e = 0; e < NEXP; e++) if (e != i1 && s[e] > s[i2]) i2 = e;
        float m = s[i1];
        float denom = 0.f;
#pragma unroll
        for (int e = 0; e < NEXP; e++) denom += expf(s[e] - m);
        float p1 = expf(s[i1] - m) / denom;
        float p2 = expf(s[i2] - m) / denom;
        float inv = 1.f / (p1 + p2 + 1e-8f);
        g_tope[tok * 2 + 0] = i1; g_topw[tok * 2 + 0] = p1 * inv;
        g_tope[tok * 2 + 1] = i2; g_topw[tok * 2 + 1] = p2 * inv;
        atomicAdd(&g_cnt[i1], 1);
        atomicAdd(&g_cnt[i2], 1);
    }
}

__global__ void k_offsets() {
    int tileE[MAXTILES];
    int run = 0;
    for (int e = 0; e < NEXP; e++) {
        g_off[e] = run;
        int ntile = (g_cnt[e] + BM - 1) / BM;
        for (int t = 0; t < ntile; t++) tileE[run / BM + t] = e;
        run += ntile * BM;
    }
    int used = run / BM;
    for (int t = 0; t < MAXTILES; t++) g_texp[t] = (t < used) ? tileE[t] : -1;
}

__global__ void k_scatter() {
    int i = blockIdx.x * blockDim.x + threadIdx.x;
    if (i >= N_TOK * 2) return;
    int e = g_tope[i];
    int pos = atomicAdd(&g_cur[e], 1);
    int slot = g_off[e] + pos;
    g_perm[slot] = i >> 1;
    g_gate[slot] = g_topw[i];
}

// ---------------- fp16 grouped GEMM: 128 threads, warp tile 64x64 ----------------
// 4 warps in 2x2; per ks-step: 8 LDSM.x4 feed 32 HMMA (4.0 mma/ldsm).
template<int KDIM, int NDIM, bool FIRST>
__global__ __launch_bounds__(128, 2) void k_gemm(
    const __half* __restrict__ Bt,
    const float* __restrict__ bias,
    float* __restrict__ Out)
{
    extern __shared__ char smem[];
    const int tileM = blockIdx.y;
    const int e = g_texp[tileM];
    if (e < 0) return;
    const int rowBase = tileM * BM;
    const int colBase = blockIdx.x * BN;

    const uint32_t sb = smem_u32(smem);
    const int tid  = threadIdx.x;
    const int lane = tid & 31;
    const int warp = tid >> 5;
    const int warpM = warp & 1;
    const int warpN = warp >> 1;

    // ---- staging maps: thread t -> rows (t>>3)+16i (i=0..7), chunk t&7 ----
    const int trow = tid >> 3;          // 0..15
    const int tch  = tid & 7;
    const __half* A = FIRST ? g_xh : g_hbuf;
    const __half* Bmat = Bt + (size_t)e * NDIM * KDIM;

    const __half* aSrc[8];
#pragma unroll
    for (int i = 0; i < 8; i++) {
        int slot = rowBase + trow + 16 * i;
        int src;
        if (FIRST) { int t = g_perm[slot]; src = (t < 0) ? 0 : t; }
        else       { src = slot; }
        aSrc[i] = A + (size_t)src * KDIM + tch * 8;
    }
    const __half* bSrc0 = Bmat + (size_t)(colBase + trow) * KDIM + tch * 8;

    uint32_t dOff[8];
#pragma unroll
    for (int i = 0; i < 8; i++) {
        int row = trow + 16 * i;
        dOff[i] = row * 128 + ((tch ^ (row & 7)) << 4);
    }

    // ---- fragment address precompute ----
    const int laneRowOff = (lane & 7) + ((lane >> 3) & 1) * 8;
    const int csel = lane >> 4;
    const int xr   = lane & 7;
    uint32_t aRB[4], bRB[4];
#pragma unroll
    for (int mt = 0; mt < 4; mt++) aRB[mt] = (warpM * 64 + mt * 16 + laneRowOff) * 128;
#pragma unroll
    for (int np = 0; np < 4; np++) bRB[np] = (warpN * 64 + np * 16 + laneRowOff) * 128;

    float acc[4][8][4];
#pragma unroll
    for (int mt = 0; mt < 4; mt++)
#pragma unroll
        for (int nt = 0; nt < 8; nt++)
#pragma unroll
            for (int i = 0; i < 4; i++) acc[mt][nt][i] = 0.f;

    const int NKB = KDIM / BK;

    // ---- prologue: issue stages 0, 1 ----
#pragma unroll
    for (int s = 0; s < NSTAGE - 1; s++) {
        uint32_t stA = sb + s * STG_BYTES;
        uint32_t stB = stA + STG_A_BYTES;
#pragma unroll
        for (int i = 0; i < 8; i++) CPA16(stA + dOff[i], aSrc[i] + s * BK);
#pragma unroll
        for (int i = 0; i < 8; i++) CPA16(stB + dOff[i], bSrc0 + (size_t)(16 * i) * KDIM + s * BK);
        CPA_COMMIT();
    }

    int buf = 0;
    for (int kb = 0; kb < NKB; kb++) {
        CPA_WAIT1();
        __syncthreads();
        if (kb + 2 < NKB) {
            int nb = buf + 2; if (nb >= NSTAGE) nb -= NSTAGE;
            uint32_t stA = sb + nb * STG_BYTES;
            uint32_t stB = stA + STG_A_BYTES;
            const int k0 = (kb + 2) * BK;
#pragma unroll
            for (int i = 0; i < 8; i++) CPA16(stA + dOff[i], aSrc[i] + k0);
#pragma unroll
            for (int i = 0; i < 8; i++) CPA16(stB + dOff[i], bSrc0 + (size_t)(16 * i) * KDIM + k0);
        }
        CPA_COMMIT();

        const uint32_t stA = sb + buf * STG_BYTES;
        const uint32_t stB = stA + STG_A_BYTES;
#pragma unroll
        for (int ks = 0; ks < 4; ks++) {
            const uint32_t sw = (uint32_t)(((2 * ks + csel) ^ xr) << 4);
            unsigned af[4][4], bf[4][4];
#pragma unroll
            for (int mt = 0; mt < 4; mt++) LDSM4(af[mt], stA + aRB[mt] + sw);
#pragma unroll
            for (int np = 0; np < 4; np++) LDSM4(bf[np], stB + bRB[np] + sw);
#pragma unroll
            for (int mt = 0; mt < 4; mt++)
#pragma unroll
                for (int nt = 0; nt < 8; nt++) {
                    const unsigned b0 = bf[nt >> 1][nt & 1];
                    const unsigned b1 = bf[nt >> 1][2 + (nt & 1)];
                    asm volatile(
                        "mma.sync.aligned.m16n8k16.row.col.f32.f16.f16.f32 "
                        "{%0,%1,%2,%3},{%4,%5,%6,%7},{%8,%9},{%0,%1,%2,%3};"
                        : "+f"(acc[mt][nt][0]), "+f"(acc[mt][nt][1]),
                          "+f"(acc[mt][nt][2]), "+f"(acc[mt][nt][3])
                        : "r"(af[mt][0]), "r"(af[mt][1]), "r"(af[mt][2]), "r"(af[mt][3]),
                          "r"(b0), "r"(b1));
                }
        }
        buf++; if (buf == NSTAGE) buf = 0;
    }
    CPA_WAIT0();

    // ---------------- epilogue ----------------
    const float* be = bias + (size_t)e * NDIM;
    if (FIRST) {
#pragma unroll
        for (int mt = 0; mt < 4; mt++) {
#pragma unroll
            for (int hh = 0; hh < 2; hh++) {
                int r = rowBase + warpM * 64 + mt * 16 + (lane >> 2) + hh * 8;
#pragma unroll
                for (int nt = 0; nt < 8; nt++) {
                    int c = colBase + warpN * 64 + nt * 8 + (lane & 3) * 2;
                    float v0 = acc[mt][nt][hh * 2 + 0] + be[c];
                    float v1 = acc[mt][nt][hh * 2 + 1] + be[c + 1];
                    v0 = v0 > 0.f ? v0 : 0.f;
                    v1 = v1 > 0.f ? v1 : 0.f;
                    *(__half2*)&g_hbuf[(size_t)r * DIMH + c] = __floats2half2_rn(v0, v1);
                }
            }
        }
    } else {
#pragma unroll
        for (int mt = 0; mt < 4; mt++) {
#pragma unroll
            for (int hh = 0; hh < 2; hh++) {
                int slot = rowBase + warpM * 64 + mt * 16 + (lane >> 2) + hh * 8;
                int tokn = g_perm[slot];
                if (tokn < 0) continue;
                float w = g_gate[slot];
#pragma unroll
                for (int nt = 0; nt < 8; nt++) {
                    int c = colBase + warpN * 64 + nt * 8 + (lane & 3) * 2;
                    atomicAdd(&Out[(size_t)tokn * DIMO + c],
                              w * (acc[mt][nt][hh * 2 + 0] + be[c]));
                    atomicAdd(&Out[(size_t)tokn * DIMO + c + 1],
                              w * (acc[mt][nt][hh * 2 + 1] + be[c + 1]));
                }
            }
        }
    }
}

// ---------------- launch ----------------
extern "C" void kernel_launch(void* const* d_in, const int* in_sizes, int n_in,
                              void* d_out, int out_size) {
    const float* x  = (const float*)d_in[0];
    const float* Wg = (const float*)d_in[1];
    const float* bg = (const float*)d_in[2];
    const float* W1 = (const float*)d_in[3];
    const float* b1 = (const float*)d_in[4];
    const float* W2 = (const float*)d_in[5];
    const float* b2 = (const float*)d_in[6];
    float* out = (float*)d_out;

    __half *w1t, *w2t;
    cudaGetSymbolAddress((void**)&w1t, g_w1t);
    cudaGetSymbolAddress((void**)&w2t, g_w2t);

    cudaFuncSetAttribute(k_gemm<DIMD, DIMH, true>,
                         cudaFuncAttributeMaxDynamicSharedMemorySize, SMEM_TOT);
    cudaFuncSetAttribute(k_gemm<DIMH, DIMO, false>,
                         cudaFuncAttributeMaxDynamicSharedMemorySize, SMEM_TOT);

    cudaMemsetAsync(d_out, 0, (size_t)N_TOK * DIMO * sizeof(float));
    k_init<<<(MAXSLOTS + 255) / 256, 256>>>();
    k_cvt_x<<<(N_TOK * DIMD / 4 + 255) / 256, 256>>>(x);
    k_tr<DIMD, DIMH><<<dim3(DIMD / 32, DIMH / 32, NEXP), dim3(32, 8)>>>(W1, w1t);
    k_tr<DIMH, DIMO><<<dim3(DIMH / 32, DIMO / 32, NEXP), dim3(32, 8)>>>(W2, w2t);
    k_gate<<<N_TOK / 8, 256>>>(x, Wg, bg);
    k_offsets<<<1, 1>>>();
    k_scatter<<<(N_TOK * 2 + 255) / 256, 256>>>();
    k_gemm<DIMD, DIMH, true ><<<dim3(DIMH / BN, MAXTILES), 128, SMEM_TOT>>>(w1t, b1, nullptr);
    k_gemm<DIMH, DIMO, false><<<dim3(DIMO / BN, MAXTILES), 128, SMEM_TOT>>>(w2t, b2, out);
}